// round 16
// baseline (speedup 1.0000x reference)
#include <cuda_runtime.h>
#include <cuda_bf16.h>
#include <cuda_fp16.h>
#include <stdint.h>

#define NN     100000
#define EE     1600000
#define IND    165
#define HID    64

// Scratch (device globals — no allocation allowed)
__device__ __align__(16) unsigned short g_y[NN * HID];   // fp16 messages, layer 1
__device__ __align__(16) unsigned short g_y2[NN * HID];  // fp16 messages, layer 2
__device__ __align__(16) unsigned short g_h[NN * HID];   // fp16 root / hidden state
__device__ int   g_deg[NN];
__device__ int   g_off[NN + 1];
__device__ int   g_cursor[NN];
__device__ int   g_csr[EE];
__device__ int   g_bsum[128];

// Precomputed fp16 B in MMA-fragment order: [wn][s][t][lane] -> uint4
__device__ __align__(16) uint4 g_bf1[2816];   // 4*11*2*32
__device__ __align__(16) uint4 g_bf2[1024];   // 4*4*2*32

// ---------------------------------------------------------------------------
#define MMA_F16(d, a, b0, b1)                                                  \
  asm volatile(                                                                \
      "mma.sync.aligned.m16n8k16.row.col.f32.f16.f16.f32 "                     \
      "{%0,%1,%2,%3},{%4,%5,%6,%7},{%8,%9},{%0,%1,%2,%3};"                     \
      : "+f"(d[0]), "+f"(d[1]), "+f"(d[2]), "+f"(d[3])                         \
      : "r"(a[0]), "r"(a[1]), "r"(a[2]), "r"(a[3]), "r"(b0), "r"(b1))

__device__ __forceinline__ void ldsm_x4(uint32_t* r, uint32_t addr)
{
    asm volatile("ldmatrix.sync.aligned.m8n8.x4.shared.b16 {%0,%1,%2,%3}, [%4];"
                 : "=r"(r[0]), "=r"(r[1]), "=r"(r[2]), "=r"(r[3]) : "r"(addr));
}

// Pack two fp32 into one fp16x2 word
__device__ __forceinline__ uint32_t pack2h(float x0, float x1)
{
    const __half2 p = __floats2half2_rn(x0, x1);
    return *(const uint32_t*)&p;
}

// ---------------------------------------------------------------------------
// Weight fragment precompute (fp16, fragment mapping unchanged)
// ---------------------------------------------------------------------------
__device__ __forceinline__ uint32_t pack_pair_w(const float* Wl, const float* Wr,
                                                int n, int k, int K)
{
    const float* Wsrc = (n < 64) ? (Wl + n) : (Wr + (n - 64));
    const float x0 = (k < K)     ? Wsrc[k * 64]       : 0.f;
    const float x1 = (k + 1 < K) ? Wsrc[(k + 1) * 64] : 0.f;
    return pack2h(x0, x1);
}

template <int K, int KSTEPS>
__device__ __forceinline__ void prep_frag(const float* Wl, const float* Wr,
                                          uint4* fh, int tid0, int stride)
{
    const int total = 4 * KSTEPS * 2 * 32;
    for (int i = tid0; i < total; i += stride) {
        const int lane = i & 31;
        const int t    = (i >> 5) & 1;
        const int s    = (i >> 6) % KSTEPS;
        const int wn   = (i >> 6) / KSTEPS;
        const int n0   = wn * 32 + t * 16 + (lane >> 2);
        const int k0   = s * 16 + 2 * (lane & 3);
        uint4 h;
        h.x = pack_pair_w(Wl, Wr, n0,     k0,     K);
        h.y = pack_pair_w(Wl, Wr, n0,     k0 + 8, K);
        h.z = pack_pair_w(Wl, Wr, n0 + 8, k0,     K);
        h.w = pack_pair_w(Wl, Wr, n0 + 8, k0 + 8, K);
        fh[i] = h;
    }
}

// W1 fragments + deg zeroing — gemm1's sole dependency
__global__ void prep_W1(const float* __restrict__ W1l, const float* __restrict__ W1r,
                        int n)
{
    const int tid0 = blockIdx.x * blockDim.x + threadIdx.x;
    const int stride = gridDim.x * blockDim.x;
    prep_frag<IND, 11>(W1l, W1r, g_bf1, tid0, stride);
    for (int i = tid0; i < n; i += stride) g_deg[i] = 0;
}

// W2 fragments — runs after csr_fill, hidden under gather1
__global__ void prep_W2(const float* __restrict__ W2l, const float* __restrict__ W2r)
{
    const int tid0 = blockIdx.x * blockDim.x + threadIdx.x;
    const int stride = gridDim.x * blockDim.x;
    prep_frag<HID, 4>(W2l, W2r, g_bf2, tid0, stride);
}

// ---------------------------------------------------------------------------
// Layer-1 GEMM: A = x fp32 global; outL = fp16(x@W1l), outR = fp16(x@W1r)
// ---------------------------------------------------------------------------
template <int K, int KPAD, int SA>
__global__ void __launch_bounds__(512, 2)
gemm_mma(const float* __restrict__ A, int nrows,
         const uint4* __restrict__ Bf,
         __half* __restrict__ outL, __half* __restrict__ outR)
{
    constexpr int W = SA / 2;
    constexpr int KSTEPS = KPAD / 16;
    constexpr int PAIRS = (K + 1) / 2;

    extern __shared__ __align__(16) unsigned char smem_raw[];
    __half* Ah = (__half*)smem_raw;             // [128][SA]
    uint32_t* Ah32 = (uint32_t*)Ah;

    const int tid  = threadIdx.x;
    const int row0 = blockIdx.x * 128;
    int valid = nrows - row0; if (valid > 128) valid = 128;

    if (valid == 128) {
        constexpr int PADW = W - PAIRS;
        if (PADW > 0) {
            for (int i = tid; i < 128 * PADW; i += 512) {
                const int r = i / PADW;
                const int p = PAIRS + (i - r * PADW);
                Ah32[r * W + p] = 0;
            }
        }
    } else {
        int4* zp = (int4*)smem_raw;
        constexpr int NZ = (128 * SA * 2) / 16;
#pragma unroll 4
        for (int i = tid; i < NZ; i += 512) zp[i] = make_int4(0, 0, 0, 0);
        __syncthreads();
    }

    // ---- stage A as fp16; unroll 8 so ptxas front-batches the loads ----
    {
        const float* Ab = A + (size_t)row0 * K;
        const int n = valid * PAIRS;
#pragma unroll 8
        for (int i = tid; i < n; i += 512) {
            const int r = i / PAIRS;
            const int p = i - r * PAIRS;
            const float* row = Ab + (size_t)r * K + 2 * p;
            const float x0 = row[0];
            const float x1 = (2 * p + 1 < K) ? row[1] : 0.f;
            Ah32[r * W + p] = pack2h(x0, x1);
        }
    }
    __syncthreads();

    // ---- MMA mainloop ----
    const int lane = tid & 31, wid = tid >> 5;
    const int wm = wid >> 2, wn = wid & 3;
    const int lr = lane >> 2, lc = lane & 3;

    const uint32_t AhB = (uint32_t)__cvta_generic_to_shared(Ah);
    const uint32_t a_base = ((wm * 32 + (lane & 15)) * W + ((lane >> 4) << 2)) * 4;
    const uint4* bf = Bf + (size_t)wn * KSTEPS * 2 * 32 + lane;

    float acc[2][4][4];
#pragma unroll
    for (int mt = 0; mt < 2; mt++)
#pragma unroll
        for (int nt = 0; nt < 4; nt++)
#pragma unroll
            for (int q = 0; q < 4; q++) acc[mt][nt][q] = 0.f;

#pragma unroll
    for (int s = 0; s < KSTEPS; s++) {
        const uint32_t so = (s * 8) * 4;
        uint32_t ah[2][4];
#pragma unroll
        for (int mt = 0; mt < 2; mt++) {
            const uint32_t off = a_base + so + mt * (16 * W * 4);
            ldsm_x4(ah[mt], AhB + off);
        }
#pragma unroll
        for (int t = 0; t < 2; t++) {
            const int fi = (s * 2 + t) * 32;
            const uint4 bh = bf[fi];
#pragma unroll
            for (int mt = 0; mt < 2; mt++) {
                MMA_F16(acc[mt][2 * t],     ah[mt], bh.x, bh.y);
                MMA_F16(acc[mt][2 * t + 1], ah[mt], bh.z, bh.w);
            }
        }
    }

    // ---- epilogue: both halves fp16 ----
#pragma unroll
    for (int mt = 0; mt < 2; mt++) {
#pragma unroll
        for (int nt = 0; nt < 4; nt++) {
            const int colb = wn * 32 + nt * 8;
            const int col = (colb + 2 * lc) & 63;
            const int row = wm * 32 + mt * 16 + lr;
            __half* o = (colb < 64) ? outL : outR;
            if (row < valid) {
                __half2 v = __float22half2_rn(make_float2(acc[mt][nt][0], acc[mt][nt][1]));
                *(__half2*)(o + (size_t)(row0 + row) * 64 + col) = v;
            }
            if (row + 8 < valid) {
                __half2 v = __float22half2_rn(make_float2(acc[mt][nt][2], acc[mt][nt][3]));
                *(__half2*)(o + (size_t)(row0 + row + 8) * 64 + col) = v;
            }
        }
    }
}

// ---------------------------------------------------------------------------
// Layer-2 GEMM: A = h fp16 global (straight coalesced copy into smem)
// ---------------------------------------------------------------------------
__global__ void __launch_bounds__(512, 2)
gemm2_h(const __half* __restrict__ Hin, int nrows,
        const uint4* __restrict__ Bf,
        __half* __restrict__ outL, __half* __restrict__ outR)
{
    constexpr int SA = 72, W = 36, KSTEPS = 4;

    extern __shared__ __align__(16) unsigned char smem_raw[];
    __half* Ah = (__half*)smem_raw;             // [128][72]
    uint32_t* Ah32 = (uint32_t*)Ah;

    const int tid  = threadIdx.x;
    const int row0 = blockIdx.x * 128;
    int valid = nrows - row0; if (valid > 128) valid = 128;

    if (valid < 128) {
        int4* zp = (int4*)smem_raw;
        constexpr int NZ = (128 * SA * 2) / 16;
#pragma unroll 4
        for (int i = tid; i < NZ; i += 512) zp[i] = make_int4(0, 0, 0, 0);
        __syncthreads();
    }

    // ---- stage A: straight fp16 copy (8 uint4 per row) ----
    {
        const uint4* Hb = (const uint4*)(Hin + (size_t)row0 * 64);
        const int n4 = valid * 8;
#pragma unroll 2
        for (int i = tid; i < n4; i += 512) {
            const int r = i >> 3;
            const int c = i & 7;
            *(uint4*)(Ah32 + r * W + c * 4) = Hb[i];
        }
    }
    // pad words 32..35 (k = 64..71)
    {
        const int r = tid >> 2;
        const int p = 32 + (tid & 3);
        Ah32[r * W + p] = 0;
    }
    __syncthreads();

    // ---- MMA mainloop ----
    const int lane = tid & 31, wid = tid >> 5;
    const int wm = wid >> 2, wn = wid & 3;
    const int lr = lane >> 2, lc = lane & 3;

    const uint32_t AhB = (uint32_t)__cvta_generic_to_shared(Ah);
    const uint32_t a_base = ((wm * 32 + (lane & 15)) * W + ((lane >> 4) << 2)) * 4;
    const uint4* bf = Bf + (size_t)wn * KSTEPS * 2 * 32 + lane;

    float acc[2][4][4];
#pragma unroll
    for (int mt = 0; mt < 2; mt++)
#pragma unroll
        for (int nt = 0; nt < 4; nt++)
#pragma unroll
            for (int q = 0; q < 4; q++) acc[mt][nt][q] = 0.f;

#pragma unroll
    for (int s = 0; s < KSTEPS; s++) {
        const uint32_t so = (s * 8) * 4;
        uint32_t ah[2][4];
#pragma unroll
        for (int mt = 0; mt < 2; mt++) {
            const uint32_t off = a_base + so + mt * (16 * W * 4);
            ldsm_x4(ah[mt], AhB + off);
        }
#pragma unroll
        for (int t = 0; t < 2; t++) {
            const int fi = (s * 2 + t) * 32;
            const uint4 bh = bf[fi];
#pragma unroll
            for (int mt = 0; mt < 2; mt++) {
                MMA_F16(acc[mt][2 * t],     ah[mt], bh.x, bh.y);
                MMA_F16(acc[mt][2 * t + 1], ah[mt], bh.z, bh.w);
            }
        }
    }

#pragma unroll
    for (int mt = 0; mt < 2; mt++) {
#pragma unroll
        for (int nt = 0; nt < 4; nt++) {
            const int colb = wn * 32 + nt * 8;
            const int col = (colb + 2 * lc) & 63;
            const int row = wm * 32 + mt * 16 + lr;
            __half* o = (colb < 64) ? outL : outR;
            if (row < valid) {
                __half2 v = __float22half2_rn(make_float2(acc[mt][nt][0], acc[mt][nt][1]));
                *(__half2*)(o + (size_t)(row0 + row) * 64 + col) = v;
            }
            if (row + 8 < valid) {
                __half2 v = __float22half2_rn(make_float2(acc[mt][nt][2], acc[mt][nt][3]));
                *(__half2*)(o + (size_t)(row0 + row + 8) * 64 + col) = v;
            }
        }
    }
}

// ---------------------------------------------------------------------------
__device__ __forceinline__ void acc_h8(float* acc, const uint4& v)
{
    const __half2* h2 = (const __half2*)&v;
#pragma unroll
    for (int j = 0; j < 4; j++) {
        const float2 f = __half22float2(h2[j]);
        acc[2 * j]     += f.x;
        acc[2 * j + 1] += f.y;
    }
}

__device__ __forceinline__ void unpack_h8(float* dst, const uint4& v)
{
    const __half2* h2 = (const __half2*)&v;
#pragma unroll
    for (int j = 0; j < 4; j++) {
        const float2 f = __half22float2(h2[j]);
        dst[2 * j]     = f.x;
        dst[2 * j + 1] = f.y;
    }
}

// ---------------------------------------------------------------------------
// Gather(mean) + bias + root + ReLU. 8 lanes per node, unroll 4.
// ---------------------------------------------------------------------------
__global__ void gather_relu(const __half* __restrict__ y,
                            const float* __restrict__ bias,
                            __half* __restrict__ hio, int n)
{
    const int tid = threadIdx.x;
    const int node = blockIdx.x * 32 + (tid >> 3);
    if (node >= n) return;
    const int l8 = (tid & 7) << 3;

    const int s = g_off[node];
    const int e = g_off[node + 1];

    float acc[8] = {0.f, 0.f, 0.f, 0.f, 0.f, 0.f, 0.f, 0.f};
    int p = s;
    for (; p + 4 <= e; p += 4) {
        const int s0 = g_csr[p], s1 = g_csr[p + 1], s2 = g_csr[p + 2], s3 = g_csr[p + 3];
        const uint4 v0 = *(const uint4*)(y + (size_t)s0 * 64 + l8);
        const uint4 v1 = *(const uint4*)(y + (size_t)s1 * 64 + l8);
        const uint4 v2 = *(const uint4*)(y + (size_t)s2 * 64 + l8);
        const uint4 v3 = *(const uint4*)(y + (size_t)s3 * 64 + l8);
        acc_h8(acc, v0); acc_h8(acc, v1); acc_h8(acc, v2); acc_h8(acc, v3);
    }
    for (; p < e; p++) {
        const uint4 v = *(const uint4*)(y + (size_t)g_csr[p] * 64 + l8);
        acc_h8(acc, v);
    }

    const float inv = 1.0f / fmaxf((float)(e - s), 1.0f);
    __half* hrow = hio + (size_t)node * 64 + l8;
    const uint4 rv = *(const uint4*)hrow;
    float rt[8];
    unpack_h8(rt, rv);
    float o[8];
#pragma unroll
    for (int j = 0; j < 8; j++)
        o[j] = fmaxf(acc[j] * inv + bias[l8 + j] + rt[j], 0.f);
    uint4 w;
    w.x = pack2h(o[0], o[1]);
    w.y = pack2h(o[2], o[3]);
    w.z = pack2h(o[4], o[5]);
    w.w = pack2h(o[6], o[7]);
    *(uint4*)hrow = w;
}

// ---------------------------------------------------------------------------
// CSR construction (R9-proven 4-wide kernels)
// ---------------------------------------------------------------------------
__global__ void degree_vec(const int* __restrict__ ei, int E)
{
    const int q = blockIdx.x * blockDim.x + threadIdx.x;
    const int e4 = q << 2;
    if (e4 + 4 <= E) {
        const int4 d = *(const int4*)(ei + E + e4);
        atomicAdd(&g_deg[d.x], 1);
        atomicAdd(&g_deg[d.y], 1);
        atomicAdd(&g_deg[d.z], 1);
        atomicAdd(&g_deg[d.w], 1);
    } else {
        for (int e = e4; e < E; e++) atomicAdd(&g_deg[ei[E + e]], 1);
    }
}

__global__ void degree_scalar(const int* __restrict__ ei, int E)
{
    const int e = blockIdx.x * blockDim.x + threadIdx.x;
    if (e < E) atomicAdd(&g_deg[ei[E + e]], 1);
}

__global__ void scan1(int n)
{
    __shared__ int wsum[32];
    const int i = blockIdx.x * 1024 + threadIdx.x;
    const int lane = threadIdx.x & 31, w = threadIdx.x >> 5;
    const int v = (i < n) ? g_deg[i] : 0;
    int inc = v;
#pragma unroll
    for (int off = 1; off < 32; off <<= 1) {
        const int t = __shfl_up_sync(0xffffffffu, inc, off);
        if (lane >= off) inc += t;
    }
    if (lane == 31) wsum[w] = inc;
    __syncthreads();
    if (w == 0) {
        const int s = wsum[lane];
        int si = s;
#pragma unroll
        for (int off = 1; off < 32; off <<= 1) {
            const int t = __shfl_up_sync(0xffffffffu, si, off);
            if (lane >= off) si += t;
        }
        wsum[lane] = si - s;
        if (lane == 31) g_bsum[blockIdx.x] = si;
    }
    __syncthreads();
    if (i < n) g_off[i] = inc - v + wsum[w];
}

// Apply block-sum prefix + init cursors (warp-reduce; i>>10 const per block)
__global__ void scan23(int n, int E, int nb)
{
    __shared__ int wred[8];
    const int t = threadIdx.x;
    int q = blockIdx.x >> 2;
    if (q > nb) q = nb;

    int v = (t < q) ? g_bsum[t] : 0;
#pragma unroll
    for (int off = 16; off > 0; off >>= 1)
        v += __shfl_down_sync(0xffffffffu, v, off);
    if ((t & 31) == 0) wred[t >> 5] = v;
    __syncthreads();
    if (t == 0) {
        int s = 0;
#pragma unroll
        for (int w = 0; w < 8; w++) s += wred[w];
        wred[0] = s;
    }
    __syncthreads();
    const int boff = wred[0];

    const int i = blockIdx.x * 256 + t;
    if (i < n) {
        const int o = g_off[i] + boff;
        g_off[i] = o;
        g_cursor[i] = o;
    } else if (i == n) {
        g_off[n] = E;
    }
}

__global__ void csr_fill_vec(const int* __restrict__ ei, int E)
{
    const int q = blockIdx.x * blockDim.x + threadIdx.x;
    const int e4 = q << 2;
    if (e4 + 4 <= E) {
        const int4 s = *(const int4*)(ei + e4);
        const int4 d = *(const int4*)(ei + E + e4);
        g_csr[atomicAdd(&g_cursor[d.x], 1)] = s.x;
        g_csr[atomicAdd(&g_cursor[d.y], 1)] = s.y;
        g_csr[atomicAdd(&g_cursor[d.z], 1)] = s.z;
        g_csr[atomicAdd(&g_cursor[d.w], 1)] = s.w;
    } else {
        for (int e = e4; e < E; e++) {
            const int dst = ei[E + e];
            g_csr[atomicAdd(&g_cursor[dst], 1)] = ei[e];
        }
    }
}

__global__ void csr_fill_scalar(const int* __restrict__ ei, int E)
{
    const int e = blockIdx.x * blockDim.x + threadIdx.x;
    if (e >= E) return;
    const int dst = ei[E + e];
    g_csr[atomicAdd(&g_cursor[dst], 1)] = ei[e];
}

// ---------------------------------------------------------------------------
// Layer-2 gather with fused classifier (root read fp16)
// ---------------------------------------------------------------------------
__global__ void gather_relu_cls(const __half* __restrict__ y,
                                const float* __restrict__ bias,
                                const __half* __restrict__ root,
                                const float* __restrict__ Wc,
                                const float* __restrict__ bc,
                                float* __restrict__ out, int n)
{
    const int tid = threadIdx.x;
    const int node = blockIdx.x * 32 + (tid >> 3);
    if (node >= n) return;
    const int l8 = (tid & 7) << 3;

    const int s = g_off[node];
    const int e = g_off[node + 1];

    float acc[8] = {0.f, 0.f, 0.f, 0.f, 0.f, 0.f, 0.f, 0.f};
    int p = s;
    for (; p + 4 <= e; p += 4) {
        const int s0 = g_csr[p], s1 = g_csr[p + 1], s2 = g_csr[p + 2], s3 = g_csr[p + 3];
        const uint4 v0 = *(const uint4*)(y + (size_t)s0 * 64 + l8);
        const uint4 v1 = *(const uint4*)(y + (size_t)s1 * 64 + l8);
        const uint4 v2 = *(const uint4*)(y + (size_t)s2 * 64 + l8);
        const uint4 v3 = *(const uint4*)(y + (size_t)s3 * 64 + l8);
        acc_h8(acc, v0); acc_h8(acc, v1); acc_h8(acc, v2); acc_h8(acc, v3);
    }
    for (; p < e; p++) {
        const uint4 v = *(const uint4*)(y + (size_t)g_csr[p] * 64 + l8);
        acc_h8(acc, v);
    }

    const float inv = 1.0f / fmaxf((float)(e - s), 1.0f);
    const uint4 rv = *(const uint4*)(root + (size_t)node * 64 + l8);
    float rt[8];
    unpack_h8(rt, rv);

    float p0 = 0.f, p1 = 0.f;
#pragma unroll
    for (int j = 0; j < 8; j++) {
        const float h = fmaxf(acc[j] * inv + bias[l8 + j] + rt[j], 0.f);
        p0 += h * Wc[(l8 + j) * 2];
        p1 += h * Wc[(l8 + j) * 2 + 1];
    }
#pragma unroll
    for (int off = 4; off > 0; off >>= 1) {
        p0 += __shfl_xor_sync(0xffffffffu, p0, off, 8);
        p1 += __shfl_xor_sync(0xffffffffu, p1, off, 8);
    }
    if ((tid & 7) == 0) {
        out[(size_t)node * 2 + 0] = p0 + bc[0];
        out[(size_t)node * 2 + 1] = p1 + bc[1];
    }
}

// ---------------------------------------------------------------------------
extern "C" void kernel_launch(void* const* d_in, const int* in_sizes, int n_in,
                              void* d_out, int out_size)
{
    const float* x   = (const float*)d_in[0];
    const int*   ei  = (const int*)  d_in[1];
    const float* W1l = (const float*)d_in[2];
    const float* b1  = (const float*)d_in[3];
    const float* W1r = (const float*)d_in[4];
    const float* W2l = (const float*)d_in[5];
    const float* b2  = (const float*)d_in[6];
    const float* W2r = (const float*)d_in[7];
    const float* Wc  = (const float*)d_in[8];
    const float* bc  = (const float*)d_in[9];

    const int N = in_sizes[0] / IND;
    const int E = in_sizes[1] / 2;
    float* out = (float*)d_out;

    void *y1_v, *y2_v, *hp_v, *b1_v, *b2_v;
    cudaGetSymbolAddress(&y1_v, g_y);
    cudaGetSymbolAddress(&y2_v, g_y2);
    cudaGetSymbolAddress(&hp_v, g_h);
    cudaGetSymbolAddress(&b1_v, g_bf1);
    cudaGetSymbolAddress(&b2_v, g_bf2);
    __half* y1p = (__half*)y1_v;
    __half* y2p = (__half*)y2_v;
    __half* hp  = (__half*)hp_v;

    constexpr int SMEM1 = 128 * 184 * 2;   // 47104 B (A fp16 only)
    constexpr int SMEM2 = 128 * 72 * 2;    // 18432 B
    cudaFuncSetAttribute(gemm_mma<IND, 176, 184>,
                         cudaFuncAttributeMaxDynamicSharedMemorySize, SMEM1);
    cudaFuncSetAttribute(gemm2_h,
                         cudaFuncAttributeMaxDynamicSharedMemorySize, SMEM2);
    // Max smem carveout -> up to 4 resident 47KB blocks on gemm1 (2x occupancy)
    cudaFuncSetAttribute(gemm_mma<IND, 176, 184>,
                         cudaFuncAttributePreferredSharedMemoryCarveout, 100);
    cudaFuncSetAttribute(gemm2_h,
                         cudaFuncAttributePreferredSharedMemoryCarveout, 100);

    static cudaStream_t s_side = nullptr;
    static cudaEvent_t ev_fork = nullptr, ev_prep = nullptr,
                       ev_join = nullptr, ev_w2 = nullptr;
    if (s_side == nullptr) {
        cudaStreamCreateWithFlags(&s_side, cudaStreamNonBlocking);
        cudaEventCreateWithFlags(&ev_fork, cudaEventDisableTiming);
        cudaEventCreateWithFlags(&ev_prep, cudaEventDisableTiming);
        cudaEventCreateWithFlags(&ev_join, cudaEventDisableTiming);
        cudaEventCreateWithFlags(&ev_w2,   cudaEventDisableTiming);
    }

    const int gemm_blocks   = (N + 127) / 128;
    const int scan_blocks   = (N + 1023) / 1024;
    const int gather_blocks = (N + 31) / 32;
    const bool e_aligned    = ((E & 3) == 0);

    // ---- Fork ----
    cudaEventRecord(ev_fork, 0);
    cudaStreamWaitEvent(s_side, ev_fork, 0);

    // Side: W1 fragments + deg zero (gemm1's sole dependency)
    prep_W1<<<64, 256, 0, s_side>>>(W1l, W1r, N);
    cudaEventRecord(ev_prep, s_side);

    // Side: CSR chain
    if (e_aligned) {
        const int q = E >> 2;
        degree_vec<<<(q + 255) / 256, 256, 0, s_side>>>(ei, E);
    } else {
        degree_scalar<<<(E + 255) / 256, 256, 0, s_side>>>(ei, E);
    }
    scan1<<<scan_blocks, 1024, 0, s_side>>>(N);

    // Main: Layer-1 GEMM (waits only on W1 frags)
    cudaStreamWaitEvent(0, ev_prep, 0);
    gemm_mma<IND, 176, 184><<<gemm_blocks, 512, SMEM1>>>(
        x, N, (const uint4*)b1_v, y1p, hp);

    // Side: scan23 + csr_fill, then W2 fragments (hidden under gather1)
    scan23<<<(N + 256) / 256, 256, 0, s_side>>>(N, E, scan_blocks);
    if (e_aligned) {
        const int q = E >> 2;
        csr_fill_vec<<<(q + 255) / 256, 256, 0, s_side>>>(ei, E);
    } else {
        csr_fill_scalar<<<(E + 255) / 256, 256, 0, s_side>>>(ei, E);
    }
    cudaEventRecord(ev_join, s_side);
    prep_W2<<<64, 256, 0, s_side>>>(W2l, W2r);
    cudaEventRecord(ev_w2, s_side);

    // ---- Join CSR, then layer-1 gather ----
    cudaStreamWaitEvent(0, ev_join, 0);
    gather_relu<<<gather_blocks, 256>>>(y1p, b1, hp, N);

    // ---- Layer-2 GEMM (also needs W2 fragments) ----
    cudaStreamWaitEvent(0, ev_w2, 0);
    gemm2_h<<<gemm_blocks, 512, SMEM2>>>(hp, N, (const uint4*)b2_v, y2p, hp);

    // ---- Layer-2 gather + classifier ----
    gather_relu_cls<<<gather_blocks, 256>>>(y2p, b2, hp, Wc, bc, out, N);
}

// round 17
// speedup vs baseline: 1.0832x; 1.0832x over previous
#include <cuda_runtime.h>
#include <cuda_bf16.h>
#include <cuda_fp16.h>
#include <stdint.h>

#define NN     100000
#define EE     1600000
#define IND    165
#define HID    64

// Scratch (device globals — no allocation allowed)
__device__ __align__(16) unsigned short g_y[NN * HID];   // fp16 messages, layer 1
__device__ __align__(16) unsigned short g_y2[NN * HID];  // fp16 messages, layer 2
__device__ __align__(16) unsigned short g_h[NN * HID];   // fp16 root / hidden state
__device__ int   g_deg[NN];
__device__ int   g_off[NN + 1];
__device__ int   g_cursor[NN];
__device__ int   g_csr[EE];
__device__ int   g_bsum[128];

// Precomputed fp16 B in MMA-fragment order: [wn][s][t][lane] -> uint4
__device__ __align__(16) uint4 g_bf1[2816];   // 4*11*2*32
__device__ __align__(16) uint4 g_bf2[1024];   // 4*4*2*32

// ---------------------------------------------------------------------------
#define MMA_F16(d, a, b0, b1)                                                  \
  asm volatile(                                                                \
      "mma.sync.aligned.m16n8k16.row.col.f32.f16.f16.f32 "                     \
      "{%0,%1,%2,%3},{%4,%5,%6,%7},{%8,%9},{%0,%1,%2,%3};"                     \
      : "+f"(d[0]), "+f"(d[1]), "+f"(d[2]), "+f"(d[3])                         \
      : "r"(a[0]), "r"(a[1]), "r"(a[2]), "r"(a[3]), "r"(b0), "r"(b1))

__device__ __forceinline__ void ldsm_x4(uint32_t* r, uint32_t addr)
{
    asm volatile("ldmatrix.sync.aligned.m8n8.x4.shared.b16 {%0,%1,%2,%3}, [%4];"
                 : "=r"(r[0]), "=r"(r[1]), "=r"(r[2]), "=r"(r[3]) : "r"(addr));
}

// Pack two fp32 into one fp16x2 word
__device__ __forceinline__ uint32_t pack2h(float x0, float x1)
{
    const __half2 p = __floats2half2_rn(x0, x1);
    return *(const uint32_t*)&p;
}

// ---------------------------------------------------------------------------
// Weight fragment precompute (fp16, fragment mapping unchanged)
// ---------------------------------------------------------------------------
__device__ __forceinline__ uint32_t pack_pair_w(const float* Wl, const float* Wr,
                                                int n, int k, int K)
{
    const float* Wsrc = (n < 64) ? (Wl + n) : (Wr + (n - 64));
    const float x0 = (k < K)     ? Wsrc[k * 64]       : 0.f;
    const float x1 = (k + 1 < K) ? Wsrc[(k + 1) * 64] : 0.f;
    return pack2h(x0, x1);
}

template <int K, int KSTEPS>
__device__ __forceinline__ void prep_frag(const float* Wl, const float* Wr,
                                          uint4* fh, int tid0, int stride)
{
    const int total = 4 * KSTEPS * 2 * 32;
    for (int i = tid0; i < total; i += stride) {
        const int lane = i & 31;
        const int t    = (i >> 5) & 1;
        const int s    = (i >> 6) % KSTEPS;
        const int wn   = (i >> 6) / KSTEPS;
        const int n0   = wn * 32 + t * 16 + (lane >> 2);
        const int k0   = s * 16 + 2 * (lane & 3);
        uint4 h;
        h.x = pack_pair_w(Wl, Wr, n0,     k0,     K);
        h.y = pack_pair_w(Wl, Wr, n0,     k0 + 8, K);
        h.z = pack_pair_w(Wl, Wr, n0 + 8, k0,     K);
        h.w = pack_pair_w(Wl, Wr, n0 + 8, k0 + 8, K);
        fh[i] = h;
    }
}

// Also zeros g_deg (removes a separate memset launch)
__global__ void prep_W(const float* __restrict__ W1l, const float* __restrict__ W1r,
                       const float* __restrict__ W2l, const float* __restrict__ W2r,
                       int n)
{
    const int tid0 = blockIdx.x * blockDim.x + threadIdx.x;
    const int stride = gridDim.x * blockDim.x;
    prep_frag<IND, 11>(W1l, W1r, g_bf1, tid0, stride);
    prep_frag<HID, 4>(W2l, W2r, g_bf2, tid0, stride);
    for (int i = tid0; i < n; i += stride) g_deg[i] = 0;
}

// ---------------------------------------------------------------------------
// Layer-1 GEMM: A = x fp32 global; outL = fp16(x@W1l), outR = fp16(x@W1r)
// ---------------------------------------------------------------------------
template <int K, int KPAD, int SA>
__global__ void __launch_bounds__(512, 2)
gemm_mma(const float* __restrict__ A, int nrows,
         const uint4* __restrict__ Bf,
         __half* __restrict__ outL, __half* __restrict__ outR)
{
    constexpr int W = SA / 2;
    constexpr int KSTEPS = KPAD / 16;
    constexpr int PAIRS = (K + 1) / 2;

    extern __shared__ __align__(16) unsigned char smem_raw[];
    __half* Ah = (__half*)smem_raw;             // [128][SA]
    uint32_t* Ah32 = (uint32_t*)Ah;

    const int tid  = threadIdx.x;
    const int row0 = blockIdx.x * 128;
    int valid = nrows - row0; if (valid > 128) valid = 128;

    if (valid == 128) {
        constexpr int PADW = W - PAIRS;
        if (PADW > 0) {
            for (int i = tid; i < 128 * PADW; i += 512) {
                const int r = i / PADW;
                const int p = PAIRS + (i - r * PADW);
                Ah32[r * W + p] = 0;
            }
        }
    } else {
        int4* zp = (int4*)smem_raw;
        constexpr int NZ = (128 * SA * 2) / 16;
#pragma unroll 4
        for (int i = tid; i < NZ; i += 512) zp[i] = make_int4(0, 0, 0, 0);
        __syncthreads();
    }

    // ---- stage A as fp16 (packed 32-bit word stores) ----
    {
        const float* Ab = A + (size_t)row0 * K;
        const int n = valid * PAIRS;
        for (int i = tid; i < n; i += 512) {
            const int r = i / PAIRS;
            const int p = i - r * PAIRS;
            const float* row = Ab + (size_t)r * K + 2 * p;
            const float x0 = row[0];
            const float x1 = (2 * p + 1 < K) ? row[1] : 0.f;
            Ah32[r * W + p] = pack2h(x0, x1);
        }
    }
    __syncthreads();

    // ---- MMA mainloop ----
    const int lane = tid & 31, wid = tid >> 5;
    const int wm = wid >> 2, wn = wid & 3;
    const int lr = lane >> 2, lc = lane & 3;

    const uint32_t AhB = (uint32_t)__cvta_generic_to_shared(Ah);
    const uint32_t a_base = ((wm * 32 + (lane & 15)) * W + ((lane >> 4) << 2)) * 4;
    const uint4* bf = Bf + (size_t)wn * KSTEPS * 2 * 32 + lane;

    float acc[2][4][4];
#pragma unroll
    for (int mt = 0; mt < 2; mt++)
#pragma unroll
        for (int nt = 0; nt < 4; nt++)
#pragma unroll
            for (int q = 0; q < 4; q++) acc[mt][nt][q] = 0.f;

#pragma unroll
    for (int s = 0; s < KSTEPS; s++) {
        const uint32_t so = (s * 8) * 4;
        uint32_t ah[2][4];
#pragma unroll
        for (int mt = 0; mt < 2; mt++) {
            const uint32_t off = a_base + so + mt * (16 * W * 4);
            ldsm_x4(ah[mt], AhB + off);
        }
#pragma unroll
        for (int t = 0; t < 2; t++) {
            const int fi = (s * 2 + t) * 32;
            const uint4 bh = bf[fi];
#pragma unroll
            for (int mt = 0; mt < 2; mt++) {
                MMA_F16(acc[mt][2 * t],     ah[mt], bh.x, bh.y);
                MMA_F16(acc[mt][2 * t + 1], ah[mt], bh.z, bh.w);
            }
        }
    }

    // ---- epilogue: both halves fp16 ----
#pragma unroll
    for (int mt = 0; mt < 2; mt++) {
#pragma unroll
        for (int nt = 0; nt < 4; nt++) {
            const int colb = wn * 32 + nt * 8;
            const int col = (colb + 2 * lc) & 63;
            const int row = wm * 32 + mt * 16 + lr;
            __half* o = (colb < 64) ? outL : outR;
            if (row < valid) {
                __half2 v = __float22half2_rn(make_float2(acc[mt][nt][0], acc[mt][nt][1]));
                *(__half2*)(o + (size_t)(row0 + row) * 64 + col) = v;
            }
            if (row + 8 < valid) {
                __half2 v = __float22half2_rn(make_float2(acc[mt][nt][2], acc[mt][nt][3]));
                *(__half2*)(o + (size_t)(row0 + row + 8) * 64 + col) = v;
            }
        }
    }
}

// ---------------------------------------------------------------------------
// Layer-2 GEMM: A = h fp16 global (straight coalesced copy into smem)
// ---------------------------------------------------------------------------
__global__ void __launch_bounds__(512, 2)
gemm2_h(const __half* __restrict__ Hin, int nrows,
        const uint4* __restrict__ Bf,
        __half* __restrict__ outL, __half* __restrict__ outR)
{
    constexpr int SA = 72, W = 36, KSTEPS = 4;

    extern __shared__ __align__(16) unsigned char smem_raw[];
    __half* Ah = (__half*)smem_raw;             // [128][72]
    uint32_t* Ah32 = (uint32_t*)Ah;

    const int tid  = threadIdx.x;
    const int row0 = blockIdx.x * 128;
    int valid = nrows - row0; if (valid > 128) valid = 128;

    if (valid < 128) {
        int4* zp = (int4*)smem_raw;
        constexpr int NZ = (128 * SA * 2) / 16;
#pragma unroll 4
        for (int i = tid; i < NZ; i += 512) zp[i] = make_int4(0, 0, 0, 0);
        __syncthreads();
    }

    // ---- stage A: straight fp16 copy (8 uint4 per row) ----
    {
        const uint4* Hb = (const uint4*)(Hin + (size_t)row0 * 64);
        const int n4 = valid * 8;
#pragma unroll 2
        for (int i = tid; i < n4; i += 512) {
            const int r = i >> 3;
            const int c = i & 7;
            *(uint4*)(Ah32 + r * W + c * 4) = Hb[i];
        }
    }
    // pad words 32..35 (k = 64..71)
    {
        const int r = tid >> 2;
        const int p = 32 + (tid & 3);
        Ah32[r * W + p] = 0;
    }
    __syncthreads();

    // ---- MMA mainloop ----
    const int lane = tid & 31, wid = tid >> 5;
    const int wm = wid >> 2, wn = wid & 3;
    const int lr = lane >> 2, lc = lane & 3;

    const uint32_t AhB = (uint32_t)__cvta_generic_to_shared(Ah);
    const uint32_t a_base = ((wm * 32 + (lane & 15)) * W + ((lane >> 4) << 2)) * 4;
    const uint4* bf = Bf + (size_t)wn * KSTEPS * 2 * 32 + lane;

    float acc[2][4][4];
#pragma unroll
    for (int mt = 0; mt < 2; mt++)
#pragma unroll
        for (int nt = 0; nt < 4; nt++)
#pragma unroll
            for (int q = 0; q < 4; q++) acc[mt][nt][q] = 0.f;

#pragma unroll
    for (int s = 0; s < KSTEPS; s++) {
        const uint32_t so = (s * 8) * 4;
        uint32_t ah[2][4];
#pragma unroll
        for (int mt = 0; mt < 2; mt++) {
            const uint32_t off = a_base + so + mt * (16 * W * 4);
            ldsm_x4(ah[mt], AhB + off);
        }
#pragma unroll
        for (int t = 0; t < 2; t++) {
            const int fi = (s * 2 + t) * 32;
            const uint4 bh = bf[fi];
#pragma unroll
            for (int mt = 0; mt < 2; mt++) {
                MMA_F16(acc[mt][2 * t],     ah[mt], bh.x, bh.y);
                MMA_F16(acc[mt][2 * t + 1], ah[mt], bh.z, bh.w);
            }
        }
    }

#pragma unroll
    for (int mt = 0; mt < 2; mt++) {
#pragma unroll
        for (int nt = 0; nt < 4; nt++) {
            const int colb = wn * 32 + nt * 8;
            const int col = (colb + 2 * lc) & 63;
            const int row = wm * 32 + mt * 16 + lr;
            __half* o = (colb < 64) ? outL : outR;
            if (row < valid) {
                __half2 v = __float22half2_rn(make_float2(acc[mt][nt][0], acc[mt][nt][1]));
                *(__half2*)(o + (size_t)(row0 + row) * 64 + col) = v;
            }
            if (row + 8 < valid) {
                __half2 v = __float22half2_rn(make_float2(acc[mt][nt][2], acc[mt][nt][3]));
                *(__half2*)(o + (size_t)(row0 + row + 8) * 64 + col) = v;
            }
        }
    }
}

// ---------------------------------------------------------------------------
__device__ __forceinline__ void acc_h8(float* acc, const uint4& v)
{
    const __half2* h2 = (const __half2*)&v;
#pragma unroll
    for (int j = 0; j < 4; j++) {
        const float2 f = __half22float2(h2[j]);
        acc[2 * j]     += f.x;
        acc[2 * j + 1] += f.y;
    }
}

__device__ __forceinline__ void unpack_h8(float* dst, const uint4& v)
{
    const __half2* h2 = (const __half2*)&v;
#pragma unroll
    for (int j = 0; j < 4; j++) {
        const float2 f = __half22float2(h2[j]);
        dst[2 * j]     = f.x;
        dst[2 * j + 1] = f.y;
    }
}

// ---------------------------------------------------------------------------
// Gather(mean) + bias + root + ReLU. 8 lanes per node, unroll 4.
// root read fp16 from hio; result written fp16 to hio.
// ---------------------------------------------------------------------------
__global__ void gather_relu(const __half* __restrict__ y,
                            const float* __restrict__ bias,
                            __half* __restrict__ hio, int n)
{
    const int tid = threadIdx.x;
    const int node = blockIdx.x * 32 + (tid >> 3);
    if (node >= n) return;
    const int l8 = (tid & 7) << 3;

    const int s = g_off[node];
    const int e = g_off[node + 1];

    float acc[8] = {0.f, 0.f, 0.f, 0.f, 0.f, 0.f, 0.f, 0.f};
    int p = s;
    for (; p + 4 <= e; p += 4) {
        const int s0 = g_csr[p], s1 = g_csr[p + 1], s2 = g_csr[p + 2], s3 = g_csr[p + 3];
        const uint4 v0 = *(const uint4*)(y + (size_t)s0 * 64 + l8);
        const uint4 v1 = *(const uint4*)(y + (size_t)s1 * 64 + l8);
        const uint4 v2 = *(const uint4*)(y + (size_t)s2 * 64 + l8);
        const uint4 v3 = *(const uint4*)(y + (size_t)s3 * 64 + l8);
        acc_h8(acc, v0); acc_h8(acc, v1); acc_h8(acc, v2); acc_h8(acc, v3);
    }
    for (; p < e; p++) {
        const uint4 v = *(const uint4*)(y + (size_t)g_csr[p] * 64 + l8);
        acc_h8(acc, v);
    }

    const float inv = 1.0f / fmaxf((float)(e - s), 1.0f);
    __half* hrow = hio + (size_t)node * 64 + l8;
    const uint4 rv = *(const uint4*)hrow;
    float rt[8];
    unpack_h8(rt, rv);
    float o[8];
#pragma unroll
    for (int j = 0; j < 8; j++)
        o[j] = fmaxf(acc[j] * inv + bias[l8 + j] + rt[j], 0.f);
    uint4 w;
    w.x = pack2h(o[0], o[1]);
    w.y = pack2h(o[2], o[3]);
    w.z = pack2h(o[4], o[5]);
    w.w = pack2h(o[6], o[7]);
    *(uint4*)hrow = w;
}

// ---------------------------------------------------------------------------
// CSR construction (R9-proven 4-wide kernels)
// ---------------------------------------------------------------------------
__global__ void degree_vec(const int* __restrict__ ei, int E)
{
    const int q = blockIdx.x * blockDim.x + threadIdx.x;
    const int e4 = q << 2;
    if (e4 + 4 <= E) {
        const int4 d = *(const int4*)(ei + E + e4);
        atomicAdd(&g_deg[d.x], 1);
        atomicAdd(&g_deg[d.y], 1);
        atomicAdd(&g_deg[d.z], 1);
        atomicAdd(&g_deg[d.w], 1);
    } else {
        for (int e = e4; e < E; e++) atomicAdd(&g_deg[ei[E + e]], 1);
    }
}

__global__ void degree_scalar(const int* __restrict__ ei, int E)
{
    const int e = blockIdx.x * blockDim.x + threadIdx.x;
    if (e < E) atomicAdd(&g_deg[ei[E + e]], 1);
}

__global__ void scan1(int n)
{
    __shared__ int wsum[32];
    const int i = blockIdx.x * 1024 + threadIdx.x;
    const int lane = threadIdx.x & 31, w = threadIdx.x >> 5;
    const int v = (i < n) ? g_deg[i] : 0;
    int inc = v;
#pragma unroll
    for (int off = 1; off < 32; off <<= 1) {
        const int t = __shfl_up_sync(0xffffffffu, inc, off);
        if (lane >= off) inc += t;
    }
    if (lane == 31) wsum[w] = inc;
    __syncthreads();
    if (w == 0) {
        const int s = wsum[lane];
        int si = s;
#pragma unroll
        for (int off = 1; off < 32; off <<= 1) {
            const int t = __shfl_up_sync(0xffffffffu, si, off);
            if (lane >= off) si += t;
        }
        wsum[lane] = si - s;
        if (lane == 31) g_bsum[blockIdx.x] = si;
    }
    __syncthreads();
    if (i < n) g_off[i] = inc - v + wsum[w];
}

// Apply block-sum prefix + init cursors (warp-reduce; i>>10 const per block)
__global__ void scan23(int n, int E, int nb)
{
    __shared__ int wred[8];
    const int t = threadIdx.x;
    int q = blockIdx.x >> 2;
    if (q > nb) q = nb;

    int v = (t < q) ? g_bsum[t] : 0;
#pragma unroll
    for (int off = 16; off > 0; off >>= 1)
        v += __shfl_down_sync(0xffffffffu, v, off);
    if ((t & 31) == 0) wred[t >> 5] = v;
    __syncthreads();
    if (t == 0) {
        int s = 0;
#pragma unroll
        for (int w = 0; w < 8; w++) s += wred[w];
        wred[0] = s;
    }
    __syncthreads();
    const int boff = wred[0];

    const int i = blockIdx.x * 256 + t;
    if (i < n) {
        const int o = g_off[i] + boff;
        g_off[i] = o;
        g_cursor[i] = o;
    } else if (i == n) {
        g_off[n] = E;
    }
}

__global__ void csr_fill_vec(const int* __restrict__ ei, int E)
{
    const int q = blockIdx.x * blockDim.x + threadIdx.x;
    const int e4 = q << 2;
    if (e4 + 4 <= E) {
        const int4 s = *(const int4*)(ei + e4);
        const int4 d = *(const int4*)(ei + E + e4);
        g_csr[atomicAdd(&g_cursor[d.x], 1)] = s.x;
        g_csr[atomicAdd(&g_cursor[d.y], 1)] = s.y;
        g_csr[atomicAdd(&g_cursor[d.z], 1)] = s.z;
        g_csr[atomicAdd(&g_cursor[d.w], 1)] = s.w;
    } else {
        for (int e = e4; e < E; e++) {
            const int dst = ei[E + e];
            g_csr[atomicAdd(&g_cursor[dst], 1)] = ei[e];
        }
    }
}

__global__ void csr_fill_scalar(const int* __restrict__ ei, int E)
{
    const int e = blockIdx.x * blockDim.x + threadIdx.x;
    if (e >= E) return;
    const int dst = ei[E + e];
    g_csr[atomicAdd(&g_cursor[dst], 1)] = ei[e];
}

// ---------------------------------------------------------------------------
// Layer-2 gather with fused classifier (root read fp16)
// ---------------------------------------------------------------------------
__global__ void gather_relu_cls(const __half* __restrict__ y,
                                const float* __restrict__ bias,
                                const __half* __restrict__ root,
                                const float* __restrict__ Wc,
                                const float* __restrict__ bc,
                                float* __restrict__ out, int n)
{
    const int tid = threadIdx.x;
    const int node = blockIdx.x * 32 + (tid >> 3);
    if (node >= n) return;
    const int l8 = (tid & 7) << 3;

    const int s = g_off[node];
    const int e = g_off[node + 1];

    float acc[8] = {0.f, 0.f, 0.f, 0.f, 0.f, 0.f, 0.f, 0.f};
    int p = s;
    for (; p + 4 <= e; p += 4) {
        const int s0 = g_csr[p], s1 = g_csr[p + 1], s2 = g_csr[p + 2], s3 = g_csr[p + 3];
        const uint4 v0 = *(const uint4*)(y + (size_t)s0 * 64 + l8);
        const uint4 v1 = *(const uint4*)(y + (size_t)s1 * 64 + l8);
        const uint4 v2 = *(const uint4*)(y + (size_t)s2 * 64 + l8);
        const uint4 v3 = *(const uint4*)(y + (size_t)s3 * 64 + l8);
        acc_h8(acc, v0); acc_h8(acc, v1); acc_h8(acc, v2); acc_h8(acc, v3);
    }
    for (; p < e; p++) {
        const uint4 v = *(const uint4*)(y + (size_t)g_csr[p] * 64 + l8);
        acc_h8(acc, v);
    }

    const float inv = 1.0f / fmaxf((float)(e - s), 1.0f);
    const uint4 rv = *(const uint4*)(root + (size_t)node * 64 + l8);
    float rt[8];
    unpack_h8(rt, rv);

    float p0 = 0.f, p1 = 0.f;
#pragma unroll
    for (int j = 0; j < 8; j++) {
        const float h = fmaxf(acc[j] * inv + bias[l8 + j] + rt[j], 0.f);
        p0 += h * Wc[(l8 + j) * 2];
        p1 += h * Wc[(l8 + j) * 2 + 1];
    }
#pragma unroll
    for (int off = 4; off > 0; off >>= 1) {
        p0 += __shfl_xor_sync(0xffffffffu, p0, off, 8);
        p1 += __shfl_xor_sync(0xffffffffu, p1, off, 8);
    }
    if ((tid & 7) == 0) {
        out[(size_t)node * 2 + 0] = p0 + bc[0];
        out[(size_t)node * 2 + 1] = p1 + bc[1];
    }
}

// ---------------------------------------------------------------------------
extern "C" void kernel_launch(void* const* d_in, const int* in_sizes, int n_in,
                              void* d_out, int out_size)
{
    const float* x   = (const float*)d_in[0];
    const int*   ei  = (const int*)  d_in[1];
    const float* W1l = (const float*)d_in[2];
    const float* b1  = (const float*)d_in[3];
    const float* W1r = (const float*)d_in[4];
    const float* W2l = (const float*)d_in[5];
    const float* b2  = (const float*)d_in[6];
    const float* W2r = (const float*)d_in[7];
    const float* Wc  = (const float*)d_in[8];
    const float* bc  = (const float*)d_in[9];

    const int N = in_sizes[0] / IND;
    const int E = in_sizes[1] / 2;
    float* out = (float*)d_out;

    void *y1_v, *y2_v, *hp_v, *b1_v, *b2_v;
    cudaGetSymbolAddress(&y1_v, g_y);
    cudaGetSymbolAddress(&y2_v, g_y2);
    cudaGetSymbolAddress(&hp_v, g_h);
    cudaGetSymbolAddress(&b1_v, g_bf1);
    cudaGetSymbolAddress(&b2_v, g_bf2);
    __half* y1p = (__half*)y1_v;
    __half* y2p = (__half*)y2_v;
    __half* hp  = (__half*)hp_v;

    constexpr int SMEM1 = 128 * 184 * 2;   // 47104 B (A fp16 only)
    constexpr int SMEM2 = 128 * 72 * 2;    // 18432 B
    cudaFuncSetAttribute(gemm_mma<IND, 176, 184>,
                         cudaFuncAttributeMaxDynamicSharedMemorySize, SMEM1);
    cudaFuncSetAttribute(gemm2_h,
                         cudaFuncAttributeMaxDynamicSharedMemorySize, SMEM2);

    static cudaStream_t s_side = nullptr;
    static cudaEvent_t ev_fork = nullptr, ev_prep = nullptr, ev_join = nullptr;
    if (s_side == nullptr) {
        cudaStreamCreateWithFlags(&s_side, cudaStreamNonBlocking);
        cudaEventCreateWithFlags(&ev_fork, cudaEventDisableTiming);
        cudaEventCreateWithFlags(&ev_prep, cudaEventDisableTiming);
        cudaEventCreateWithFlags(&ev_join, cudaEventDisableTiming);
    }

    const int gemm_blocks   = (N + 127) / 128;
    const int scan_blocks   = (N + 1023) / 1024;
    const int gather_blocks = (N + 31) / 32;
    const bool e_aligned    = ((E & 3) == 0);

    // ---- Fork ----
    cudaEventRecord(ev_fork, 0);
    cudaStreamWaitEvent(s_side, ev_fork, 0);

    // Side: weight fragments (+deg zero)                [kernel #1]
    prep_W<<<64, 256, 0, s_side>>>(W1l, W1r, W2l, W2r, N);
    cudaEventRecord(ev_prep, s_side);

    // Side: degree + scan1                              [kernels #2, #3]
    if (e_aligned) {
        const int q = E >> 2;
        degree_vec<<<(q + 255) / 256, 256, 0, s_side>>>(ei, E);
    } else {
        degree_scalar<<<(E + 255) / 256, 256, 0, s_side>>>(ei, E);
    }
    scan1<<<scan_blocks, 1024, 0, s_side>>>(N);

    // Main: Layer-1 GEMM (waits only on weight frags)   [kernel #4]
    cudaStreamWaitEvent(0, ev_prep, 0);
    gemm_mma<IND, 176, 184><<<gemm_blocks, 512, SMEM1>>>(
        x, N, (const uint4*)b1_v, y1p, hp);

    // Side: scan23 + csr_fill                           [kernels #5, #6]
    scan23<<<(N + 256) / 256, 256, 0, s_side>>>(N, E, scan_blocks);
    if (e_aligned) {
        const int q = E >> 2;
        csr_fill_vec<<<(q + 255) / 256, 256, 0, s_side>>>(ei, E);
    } else {
        csr_fill_scalar<<<(E + 255) / 256, 256, 0, s_side>>>(ei, E);
    }
    cudaEventRecord(ev_join, s_side);

    // ---- Join CSR, then layer-1 gather + layer-2 GEMM ----
    cudaStreamWaitEvent(0, ev_join, 0);
    gather_relu<<<gather_blocks, 256>>>(y1p, b1, hp, N);

    gemm2_h<<<gemm_blocks, 512, SMEM2>>>(hp, N, (const uint4*)b2_v, y2p, hp);

    // ---- Layer-2 gather + classifier ----
    gather_relu_cls<<<gather_blocks, 256>>>(y2p, b2, hp, Wc, bc, out, N);
}